// round 6
// baseline (speedup 1.0000x reference)
#include <cuda_runtime.h>
#include <cuda_bf16.h>
#include <cstdint>

// ---------------------------------------------------------------------------
// Problem constants
// ---------------------------------------------------------------------------
#define Bq 2
#define Tt 2048
#define Dd 1024
#define DCc 512
#define DMm 1536
#define Hh 16
#define DEe 4096
#define DGg 1024
#define Mrows (Bq * Tt)          // 4096
#define CHD (DCc / Hh)           // 32
#define MHD (DMm / Hh)           // 96

// ---------------------------------------------------------------------------
// Scratch (device globals; cudaMalloc is forbidden)
// ---------------------------------------------------------------------------
__device__ float g_x1[Mrows * Dd];
__device__ float g_q [Mrows * DCc];
__device__ float g_k [Mrows * DCc];
__device__ float g_v [Mrows * DMm];
__device__ float g_y [Mrows * DMm];
__device__ float g_xa[Mrows * Dd];
__device__ float g_x2[Mrows * Dd];
__device__ float g_e [Mrows * DEe];
__device__ float g_sg[Mrows * DGg];
__device__ float g_g [Mrows * DEe];

// ---------------------------------------------------------------------------
// helpers
// ---------------------------------------------------------------------------
__device__ __forceinline__ uint32_t f2tf32(float f) {
    uint32_t u;
    asm("cvt.rna.tf32.f32 %0, %1;" : "=r"(u) : "f"(f));
    return u;
}

__device__ __forceinline__ void mma_tf32(float* c, const uint32_t* a, const uint32_t* b) {
    asm volatile(
        "mma.sync.aligned.m16n8k8.row.col.f32.tf32.tf32.f32 "
        "{%0,%1,%2,%3}, {%4,%5,%6,%7}, {%8,%9}, {%0,%1,%2,%3};"
        : "+f"(c[0]), "+f"(c[1]), "+f"(c[2]), "+f"(c[3])
        : "r"(a[0]), "r"(a[1]), "r"(a[2]), "r"(a[3]), "r"(b[0]), "r"(b[1]));
}

// pack two floats as bf16x2: low half = lo (even k), high half = hi (odd k)
__device__ __forceinline__ uint32_t pack_bf16(float lo, float hi) {
    uint32_t u;
    asm("cvt.rn.bf16x2.f32 %0, %1, %2;" : "=r"(u) : "f"(hi), "f"(lo));
    return u;
}

__device__ __forceinline__ void mma_bf16(float* c, const uint32_t* a, const uint32_t* b) {
    asm volatile(
        "mma.sync.aligned.m16n8k16.row.col.f32.bf16.bf16.f32 "
        "{%0,%1,%2,%3}, {%4,%5,%6,%7}, {%8,%9}, {%0,%1,%2,%3};"
        : "+f"(c[0]), "+f"(c[1]), "+f"(c[2]), "+f"(c[3])
        : "r"(a[0]), "r"(a[1]), "r"(a[2]), "r"(a[3]), "r"(b[0]), "r"(b[1]));
}

// ---------------------------------------------------------------------------
// LayerNorm (unchanged)
// ---------------------------------------------------------------------------
__global__ __launch_bounds__(256) void ln_kernel(
    const float* __restrict__ x, const float* __restrict__ w,
    const float* __restrict__ b, float* __restrict__ out)
{
    int row = blockIdx.x;
    int tid = threadIdx.x;
    const float* xr = x + (size_t)row * Dd;
    float4 v = *(const float4*)(xr + tid * 4);
    float s  = v.x + v.y + v.z + v.w;
    float sq = v.x*v.x + v.y*v.y + v.z*v.z + v.w*v.w;
    #pragma unroll
    for (int o = 16; o > 0; o >>= 1) {
        s  += __shfl_xor_sync(0xffffffffu, s,  o);
        sq += __shfl_xor_sync(0xffffffffu, sq, o);
    }
    __shared__ float ss[8], ssq[8];
    int wid = tid >> 5, lid = tid & 31;
    if (lid == 0) { ss[wid] = s; ssq[wid] = sq; }
    __syncthreads();
    s = 0.f; sq = 0.f;
    #pragma unroll
    for (int i = 0; i < 8; i++) { s += ss[i]; sq += ssq[i]; }
    float mu  = s * (1.f / Dd);
    float var = sq * (1.f / Dd) - mu * mu;
    float rs  = rsqrtf(var + 1e-5f);
    float4 wv = *(const float4*)(w + tid * 4);
    float4 bv = *(const float4*)(b + tid * 4);
    float4 o;
    o.x = (v.x - mu) * rs * wv.x + bv.x;
    o.y = (v.y - mu) * rs * wv.y + bv.y;
    o.z = (v.z - mu) * rs * wv.z + bv.z;
    o.w = (v.w - mu) * rs * wv.w + bv.w;
    *(float4*)(out + (size_t)row * Dd + tid * 4) = o;
}

// ---------------------------------------------------------------------------
// BF16 tensor-core GEMM: C = A[M,K] @ W[K,N] + bias, epilogue modes:
//   0: bias   1: bias + residual   2: bias->SiLU   3: bias->sigmoid
// 128x128x32 tile, 256 threads. M,N % 128 == 0; K % 32 == 0.
// Smem holds k-pair-packed bf16 (uint32 = two consecutive-k bf16 values).
// ---------------------------------------------------------------------------
#define PA_ST 28     // Pa row stride in uint32 (28r+q conflict-free)
#define PB_ST 136    // Pb row stride in uint32 (8q+r conflict-free)

__global__ __launch_bounds__(256) void bgemm_kernel(
    const float* __restrict__ A, const float* __restrict__ W,
    const float* __restrict__ bias, const float* __restrict__ res,
    float* __restrict__ C, int M, int N, int K, int mode)
{
    __shared__ uint32_t Pa[2][128][PA_ST];   // [m][k2], k2 = 0..15 per tile
    __shared__ uint32_t Pb[2][16][PB_ST];    // [k2][n]

    int t = threadIdx.x;
    int bm = blockIdx.y * 128;
    int bn = blockIdx.x * 128;
    int lane = t & 31, wid = t >> 5;
    int r = lane >> 2, q = lane & 3;
    int m_base = (wid & 3) * 32;
    int n_base = (wid >> 2) * 64;

    // A global: row = t>>1 (0..127), 16 consecutive floats at col (t&1)*16
    int a_row = t >> 1;
    int a_c16 = (t & 1) * 16;
    // B global: row-pair p = t>>4 (0..15), col-groups (t&15) and (t&15)+16
    int b_p  = t >> 4;
    int b_cg = t & 15;

    const int nk = K / 32;

    float acc[2][8][4];
    #pragma unroll
    for (int i = 0; i < 2; i++)
        #pragma unroll
        for (int j = 0; j < 8; j++)
            #pragma unroll
            for (int c = 0; c < 4; c++) acc[i][j][c] = 0.f;

    uint32_t pa[8], pb[2][4];

    // ---- load tile k0 into packed regs
    {
        const float* Ab = A + (size_t)(bm + a_row) * K + a_c16;
        #pragma unroll
        for (int j = 0; j < 4; j++) {
            float4 f = *(const float4*)(Ab + 4 * j);
            pa[2*j]   = pack_bf16(f.x, f.y);
            pa[2*j+1] = pack_bf16(f.z, f.w);
        }
        #pragma unroll
        for (int u = 0; u < 2; u++) {
            int cg = b_cg + u * 16;
            const float* w0 = W + (size_t)(2 * b_p) * N + bn + cg * 4;
            float4 f0 = *(const float4*)w0;
            float4 f1 = *(const float4*)(w0 + N);
            pb[u][0] = pack_bf16(f0.x, f1.x);
            pb[u][1] = pack_bf16(f0.y, f1.y);
            pb[u][2] = pack_bf16(f0.z, f1.z);
            pb[u][3] = pack_bf16(f0.w, f1.w);
        }
    }
    // ---- store tile 0
    {
        int kb = (t & 1) * 8;
        #pragma unroll
        for (int j = 0; j < 8; j++) Pa[0][a_row][kb + j] = pa[j];
        #pragma unroll
        for (int u = 0; u < 2; u++) {
            int cg = b_cg + u * 16;
            #pragma unroll
            for (int i = 0; i < 4; i++) Pb[0][b_p][cg * 4 + i] = pb[u][i];
        }
    }
    __syncthreads();

    for (int kt = 0; kt < nk; kt++) {
        int buf = kt & 1;
        if (kt + 1 < nk) {
            int k0 = (kt + 1) * 32;
            const float* Ab = A + (size_t)(bm + a_row) * K + k0 + a_c16;
            #pragma unroll
            for (int j = 0; j < 4; j++) {
                float4 f = *(const float4*)(Ab + 4 * j);
                pa[2*j]   = pack_bf16(f.x, f.y);
                pa[2*j+1] = pack_bf16(f.z, f.w);
            }
            #pragma unroll
            for (int u = 0; u < 2; u++) {
                int cg = b_cg + u * 16;
                const float* w0 = W + (size_t)(k0 + 2 * b_p) * N + bn + cg * 4;
                float4 f0 = *(const float4*)w0;
                float4 f1 = *(const float4*)(w0 + N);
                pb[u][0] = pack_bf16(f0.x, f1.x);
                pb[u][1] = pack_bf16(f0.y, f1.y);
                pb[u][2] = pack_bf16(f0.z, f1.z);
                pb[u][3] = pack_bf16(f0.w, f1.w);
            }
        }

        #pragma unroll
        for (int h = 0; h < 2; h++) {
            uint32_t a[2][4], b[8][2];
            int kb = h * 8;
            #pragma unroll
            for (int mt = 0; mt < 2; mt++) {
                int m0 = m_base + mt * 16;
                a[mt][0] = Pa[buf][m0 + r    ][kb + q];
                a[mt][1] = Pa[buf][m0 + r + 8][kb + q];
                a[mt][2] = Pa[buf][m0 + r    ][kb + q + 4];
                a[mt][3] = Pa[buf][m0 + r + 8][kb + q + 4];
            }
            #pragma unroll
            for (int nt = 0; nt < 8; nt++) {
                int n0 = n_base + nt * 8;
                b[nt][0] = Pb[buf][kb + q    ][n0 + r];
                b[nt][1] = Pb[buf][kb + q + 4][n0 + r];
            }
            #pragma unroll
            for (int mt = 0; mt < 2; mt++)
                #pragma unroll
                for (int nt = 0; nt < 8; nt++)
                    mma_bf16(acc[mt][nt], a[mt], b[nt]);
        }

        if (kt + 1 < nk) {
            int nb = buf ^ 1;
            int kb = (t & 1) * 8;
            #pragma unroll
            for (int j = 0; j < 8; j++) Pa[nb][a_row][kb + j] = pa[j];
            #pragma unroll
            for (int u = 0; u < 2; u++) {
                int cg = b_cg + u * 16;
                #pragma unroll
                for (int i = 0; i < 4; i++) Pb[nb][b_p][cg * 4 + i] = pb[u][i];
            }
            __syncthreads();
        }
    }

    // epilogue: c0,c1 -> (row0, col..col+1); c2,c3 -> (row0+8, ...)
    #pragma unroll
    for (int mt = 0; mt < 2; mt++) {
        int row0 = bm + m_base + mt * 16 + r;
        #pragma unroll
        for (int nt = 0; nt < 8; nt++) {
            int col = bn + n_base + nt * 8 + q * 2;
            float b0 = bias[col], b1 = bias[col + 1];
            float v0 = acc[mt][nt][0] + b0;
            float v1 = acc[mt][nt][1] + b1;
            float v2 = acc[mt][nt][2] + b0;
            float v3 = acc[mt][nt][3] + b1;
            if (mode == 1) {
                v0 += res[(size_t)row0 * N + col];
                v1 += res[(size_t)row0 * N + col + 1];
                v2 += res[(size_t)(row0 + 8) * N + col];
                v3 += res[(size_t)(row0 + 8) * N + col + 1];
            } else if (mode == 2) {
                v0 = v0 / (1.f + __expf(-v0));
                v1 = v1 / (1.f + __expf(-v1));
                v2 = v2 / (1.f + __expf(-v2));
                v3 = v3 / (1.f + __expf(-v3));
            } else if (mode == 3) {
                v0 = 1.f / (1.f + __expf(-v0));
                v1 = 1.f / (1.f + __expf(-v1));
                v2 = 1.f / (1.f + __expf(-v2));
                v3 = 1.f / (1.f + __expf(-v3));
            }
            *(float2*)(C + (size_t)row0 * N + col)       = make_float2(v0, v1);
            *(float2*)(C + (size_t)(row0 + 8) * N + col) = make_float2(v2, v3);
        }
    }
}

// ---------------------------------------------------------------------------
// TF32 MMA flash attention (unchanged from round 4)
// ---------------------------------------------------------------------------
#define AT_KST 36
#define AT_VST 68
#define AT_SST 68
#define ATTN_SMEM ((64*AT_KST + 96*AT_VST + 4*16*AT_SST) * 4)

__global__ __launch_bounds__(128) void attn_mma_kernel(
    const float* __restrict__ q, const float* __restrict__ k,
    const float* __restrict__ v, float* __restrict__ y)
{
    extern __shared__ float sm[];
    float* Ks = sm;
    float* Vs = Ks + 64 * AT_KST;
    float* Ss = Vs + 96 * AT_VST;

    int tid  = threadIdx.x;
    int wid  = tid >> 5, lane = tid & 31;
    int r    = lane >> 2, qd = lane & 3;
    int qt   = blockIdx.x;
    int bh   = blockIdx.y;
    int b    = bh >> 4, h = bh & 15;
    int q0   = qt * 64;
    int mrow = wid * 16;

    const float* qbase = q + (size_t)b * Tt * DCc + h * CHD;
    const float* kbase = k + (size_t)b * Tt * DCc + h * CHD;
    const float* vbase = v + (size_t)b * Tt * DMm + h * MHD;

    const float scale = 0.17677669529663687f;
    int grow0 = q0 + mrow + r;
    uint32_t qa[4][4];
    #pragma unroll
    for (int ks = 0; ks < 4; ks++) {
        qa[ks][0] = f2tf32(qbase[(size_t)grow0       * DCc + ks * 8 + qd    ] * scale);
        qa[ks][1] = f2tf32(qbase[(size_t)(grow0 + 8) * DCc + ks * 8 + qd    ] * scale);
        qa[ks][2] = f2tf32(qbase[(size_t)grow0       * DCc + ks * 8 + qd + 4] * scale);
        qa[ks][3] = f2tf32(qbase[(size_t)(grow0 + 8) * DCc + ks * 8 + qd + 4] * scale);
    }

    float m0 = -1e30f, m1 = -1e30f, l0 = 0.f, l1 = 0.f;
    float o[12][4];
    #pragma unroll
    for (int nt = 0; nt < 12; nt++)
        #pragma unroll
        for (int c = 0; c < 4; c++) o[nt][c] = 0.f;

    float* Sw = Ss + wid * 16 * AT_SST;

    for (int j = 0; j <= qt; j++) {
        int k0 = j * 64;
        __syncthreads();
        {
            int row = tid >> 1;
            int c0  = (tid & 1) * 16;
            const float* src = kbase + (size_t)(k0 + row) * DCc + c0;
            uint32_t* dst = (uint32_t*)&Ks[row * AT_KST + c0];
            #pragma unroll
            for (int jj = 0; jj < 4; jj++) {
                float4 f = *(const float4*)(src + jj * 4);
                uint4 u = make_uint4(f2tf32(f.x), f2tf32(f.y), f2tf32(f.z), f2tf32(f.w));
                *(uint4*)(dst + jj * 4) = u;
            }
        }
        {
            #pragma unroll
            for (int it = 0; it < 12; it++) {
                int idx  = it * 128 + tid;
                int trow = idx / 24, c4 = idx % 24;
                float4 f = *(const float4*)(vbase + (size_t)(k0 + trow) * DMm + c4 * 4);
                Vs[(c4 * 4 + 0) * AT_VST + trow] = __uint_as_float(f2tf32(f.x));
                Vs[(c4 * 4 + 1) * AT_VST + trow] = __uint_as_float(f2tf32(f.y));
                Vs[(c4 * 4 + 2) * AT_VST + trow] = __uint_as_float(f2tf32(f.z));
                Vs[(c4 * 4 + 3) * AT_VST + trow] = __uint_as_float(f2tf32(f.w));
            }
        }
        __syncthreads();

        float sc[8][4];
        #pragma unroll
        for (int nt = 0; nt < 8; nt++)
            #pragma unroll
            for (int c = 0; c < 4; c++) sc[nt][c] = 0.f;
        #pragma unroll
        for (int ks = 0; ks < 4; ks++) {
            #pragma unroll
            for (int nt = 0; nt < 8; nt++) {
                uint32_t bb[2];
                bb[0] = __float_as_uint(Ks[(nt * 8 + r) * AT_KST + ks * 8 + qd    ]);
                bb[1] = __float_as_uint(Ks[(nt * 8 + r) * AT_KST + ks * 8 + qd + 4]);
                mma_tf32(sc[nt], qa[ks], bb);
            }
        }

        float mx0 = -1e30f, mx1 = -1e30f;
        #pragma unroll
        for (int nt = 0; nt < 8; nt++) {
            int c = k0 + nt * 8 + 2 * qd;
            if (c     > grow0    ) sc[nt][0] = -1e30f;
            if (c + 1 > grow0    ) sc[nt][1] = -1e30f;
            if (c     > grow0 + 8) sc[nt][2] = -1e30f;
            if (c + 1 > grow0 + 8) sc[nt][3] = -1e30f;
            mx0 = fmaxf(mx0, fmaxf(sc[nt][0], sc[nt][1]));
            mx1 = fmaxf(mx1, fmaxf(sc[nt][2], sc[nt][3]));
        }
        mx0 = fmaxf(mx0, __shfl_xor_sync(0xffffffffu, mx0, 1));
        mx0 = fmaxf(mx0, __shfl_xor_sync(0xffffffffu, mx0, 2));
        mx1 = fmaxf(mx1, __shfl_xor_sync(0xffffffffu, mx1, 1));
        mx1 = fmaxf(mx1, __shfl_xor_sync(0xffffffffu, mx1, 2));

        float mn0 = fmaxf(m0, mx0), mn1 = fmaxf(m1, mx1);
        float corr0 = __expf(m0 - mn0), corr1 = __expf(m1 - mn1);
        float s0 = 0.f, s1 = 0.f;
        #pragma unroll
        for (int nt = 0; nt < 8; nt++) {
            float p00 = __expf(sc[nt][0] - mn0);
            float p01 = __expf(sc[nt][1] - mn0);
            float p10 = __expf(sc[nt][2] - mn1);
            float p11 = __expf(sc[nt][3] - mn1);
            s0 += p00 + p01;
            s1 += p10 + p11;
            int cb = nt * 8 + 2 * qd;
            Sw[r * AT_SST + cb]           = __uint_as_float(f2tf32(p00));
            Sw[r * AT_SST + cb + 1]       = __uint_as_float(f2tf32(p01));
            Sw[(r + 8) * AT_SST + cb]     = __uint_as_float(f2tf32(p10));
            Sw[(r + 8) * AT_SST + cb + 1] = __uint_as_float(f2tf32(p11));
        }
        s0 += __shfl_xor_sync(0xffffffffu, s0, 1);
        s0 += __shfl_xor_sync(0xffffffffu, s0, 2);
        s1 += __shfl_xor_sync(0xffffffffu, s1, 1);
        s1 += __shfl_xor_sync(0xffffffffu, s1, 2);
        l0 = l0 * corr0 + s0;
        l1 = l1 * corr1 + s1;
        m0 = mn0; m1 = mn1;
        #pragma unroll
        for (int nt = 0; nt < 12; nt++) {
            o[nt][0] *= corr0; o[nt][1] *= corr0;
            o[nt][2] *= corr1; o[nt][3] *= corr1;
        }
        __syncwarp();

        #pragma unroll
        for (int ks = 0; ks < 8; ks++) {
            uint32_t pa[4];
            pa[0] = __float_as_uint(Sw[r       * AT_SST + ks * 8 + qd    ]);
            pa[1] = __float_as_uint(Sw[(r + 8) * AT_SST + ks * 8 + qd    ]);
            pa[2] = __float_as_uint(Sw[r       * AT_SST + ks * 8 + qd + 4]);
            pa[3] = __float_as_uint(Sw[(r + 8) * AT_SST + ks * 8 + qd + 4]);
            #pragma unroll
            for (int nt = 0; nt < 12; nt++) {
                uint32_t bb[2];
                bb[0] = __float_as_uint(Vs[(nt * 8 + r) * AT_VST + ks * 8 + qd    ]);
                bb[1] = __float_as_uint(Vs[(nt * 8 + r) * AT_VST + ks * 8 + qd + 4]);
                mma_tf32(o[nt], pa, bb);
            }
        }
        __syncwarp();
    }

    float inv0 = 1.f / l0, inv1 = 1.f / l1;
    float* yb = y + (size_t)b * Tt * DMm + h * MHD;
    #pragma unroll
    for (int nt = 0; nt < 12; nt++) {
        int cb = nt * 8 + 2 * qd;
        *(float2*)(yb + (size_t)grow0 * DMm + cb) =
            make_float2(o[nt][0] * inv0, o[nt][1] * inv0);
        *(float2*)(yb + (size_t)(grow0 + 8) * DMm + cb) =
            make_float2(o[nt][2] * inv1, o[nt][3] * inv1);
    }
}

// ---------------------------------------------------------------------------
// elementwise: e = silu(e * g)
// ---------------------------------------------------------------------------
__global__ __launch_bounds__(256) void eg_kernel(
    float* __restrict__ e, const float* __restrict__ g, int n4)
{
    int i = blockIdx.x * blockDim.x + threadIdx.x;
    if (i >= n4) return;
    float4 a = ((float4*)e)[i];
    float4 bb = ((const float4*)g)[i];
    float t;
    t = a.x * bb.x; a.x = t / (1.f + __expf(-t));
    t = a.y * bb.y; a.y = t / (1.f + __expf(-t));
    t = a.z * bb.z; a.z = t / (1.f + __expf(-t));
    t = a.w * bb.w; a.w = t / (1.f + __expf(-t));
    ((float4*)e)[i] = a;
}

// ---------------------------------------------------------------------------
// Host launcher
// ---------------------------------------------------------------------------
extern "C" void kernel_launch(void* const* d_in, const int* in_sizes, int n_in,
                              void* d_out, int out_size)
{
    const float* x     = (const float*)d_in[0];
    const float* ln1_w = (const float*)d_in[2];
    const float* ln1_b = (const float*)d_in[3];
    const float* wq    = (const float*)d_in[4];
    const float* bq    = (const float*)d_in[5];
    const float* wk    = (const float*)d_in[6];
    const float* bk    = (const float*)d_in[7];
    const float* wv    = (const float*)d_in[8];
    const float* bv    = (const float*)d_in[9];
    const float* wo    = (const float*)d_in[10];
    const float* bo    = (const float*)d_in[11];
    const float* ln2_w = (const float*)d_in[12];
    const float* ln2_b = (const float*)d_in[13];
    const float* we    = (const float*)d_in[14];
    const float* be    = (const float*)d_in[15];
    const float* wg    = (const float*)d_in[16];
    const float* bg    = (const float*)d_in[17];
    const float* wu    = (const float*)d_in[18];
    const float* bu    = (const float*)d_in[19];
    const float* wc    = (const float*)d_in[20];
    const float* bc    = (const float*)d_in[21];
    float* out = (float*)d_out;

    float *x1, *qp, *kp, *vp, *yp, *xa, *x2, *ep, *sg, *gp;
    cudaGetSymbolAddress((void**)&x1, g_x1);
    cudaGetSymbolAddress((void**)&qp, g_q);
    cudaGetSymbolAddress((void**)&kp, g_k);
    cudaGetSymbolAddress((void**)&vp, g_v);
    cudaGetSymbolAddress((void**)&yp, g_y);
    cudaGetSymbolAddress((void**)&xa, g_xa);
    cudaGetSymbolAddress((void**)&x2, g_x2);
    cudaGetSymbolAddress((void**)&ep, g_e);
    cudaGetSymbolAddress((void**)&sg, g_sg);
    cudaGetSymbolAddress((void**)&gp, g_g);

    cudaFuncSetAttribute(attn_mma_kernel,
                         cudaFuncAttributeMaxDynamicSharedMemorySize, ATTN_SMEM);

    // 1) LN1
    ln_kernel<<<Mrows, 256>>>(x, ln1_w, ln1_b, x1);

    // 2) Q/K/V projections
    bgemm_kernel<<<dim3(DCc/128, Mrows/128), 256>>>(x1, wq, bq, nullptr, qp, Mrows, DCc, Dd, 0);
    bgemm_kernel<<<dim3(DCc/128, Mrows/128), 256>>>(x1, wk, bk, nullptr, kp, Mrows, DCc, Dd, 0);
    bgemm_kernel<<<dim3(DMm/128, Mrows/128), 256>>>(x1, wv, bv, nullptr, vp, Mrows, DMm, Dd, 0);

    // 3) causal attention (TF32 MMA)
    attn_mma_kernel<<<dim3(Tt/64, Bq*Hh), 128, ATTN_SMEM>>>(qp, kp, vp, yp);

    // 4) output projection + residual
    bgemm_kernel<<<dim3(Dd/128, Mrows/128), 256>>>(yp, wo, bo, x, xa, Mrows, Dd, DMm, 1);

    // 5) LN2
    ln_kernel<<<Mrows, 256>>>(xa, ln2_w, ln2_b, x2);

    // 6) e = x2@we + be
    bgemm_kernel<<<dim3(DEe/128, Mrows/128), 256>>>(x2, we, be, nullptr, ep, Mrows, DEe, Dd, 0);

    // 7) sg = silu(x2@wg + bg)
    bgemm_kernel<<<dim3(DGg/128, Mrows/128), 256>>>(x2, wg, bg, nullptr, sg, Mrows, DGg, Dd, 2);

    // 8) g = sigmoid(sg@wu + bu)
    bgemm_kernel<<<dim3(DEe/128, Mrows/128), 256>>>(sg, wu, bu, nullptr, gp, Mrows, DEe, DGg, 3);

    // 9) e = silu(e * g)
    {
        int n4 = Mrows * DEe / 4;
        eg_kernel<<<(n4 + 255) / 256, 256>>>(ep, gp, n4);
    }

    // 10) out = xa + e@wc + bc
    bgemm_kernel<<<dim3(Dd/128, Mrows/128), 256>>>(ep, wc, bc, xa, out, Mrows, Dd, DEe, 1);
}

// round 7
// speedup vs baseline: 1.3906x; 1.3906x over previous
#include <cuda_runtime.h>
#include <cuda_bf16.h>
#include <cstdint>

// ---------------------------------------------------------------------------
// Problem constants
// ---------------------------------------------------------------------------
#define Bq 2
#define Tt 2048
#define Dd 1024
#define DCc 512
#define DMm 1536
#define Hh 16
#define DEe 4096
#define DGg 1024
#define Mrows (Bq * Tt)          // 4096
#define CHD (DCc / Hh)           // 32
#define MHD (DMm / Hh)           // 96

// ---------------------------------------------------------------------------
// Scratch (device globals; cudaMalloc is forbidden)
// ---------------------------------------------------------------------------
__device__ float g_x1[Mrows * Dd];
__device__ float g_q [Mrows * DCc];
__device__ float g_k [Mrows * DCc];
__device__ float g_v [Mrows * DMm];
__device__ float g_y [Mrows * DMm];
__device__ float g_xa[Mrows * Dd];
__device__ float g_x2[Mrows * Dd];
__device__ float g_e [Mrows * DEe];
__device__ float g_sg[Mrows * DGg];
__device__ float g_g [Mrows * DEe];

// ---------------------------------------------------------------------------
// helpers
// ---------------------------------------------------------------------------
__device__ __forceinline__ uint32_t f2tf32(float f) {
    uint32_t u;
    asm("cvt.rna.tf32.f32 %0, %1;" : "=r"(u) : "f"(f));
    return u;
}

__device__ __forceinline__ void mma_tf32(float* c, const uint32_t* a, const uint32_t* b) {
    asm volatile(
        "mma.sync.aligned.m16n8k8.row.col.f32.tf32.tf32.f32 "
        "{%0,%1,%2,%3}, {%4,%5,%6,%7}, {%8,%9}, {%0,%1,%2,%3};"
        : "+f"(c[0]), "+f"(c[1]), "+f"(c[2]), "+f"(c[3])
        : "r"(a[0]), "r"(a[1]), "r"(a[2]), "r"(a[3]), "r"(b[0]), "r"(b[1]));
}

__device__ __forceinline__ void cp_async16(void* smem, const void* gmem) {
    uint32_t s = (uint32_t)__cvta_generic_to_shared(smem);
    asm volatile("cp.async.cg.shared.global [%0], [%1], 16;" :: "r"(s), "l"(gmem));
}
__device__ __forceinline__ void cp_commit() {
    asm volatile("cp.async.commit_group;");
}
template <int N>
__device__ __forceinline__ void cp_wait() {
    asm volatile("cp.async.wait_group %0;" :: "n"(N));
}

// ---------------------------------------------------------------------------
// LayerNorm (unchanged)
// ---------------------------------------------------------------------------
__global__ __launch_bounds__(256) void ln_kernel(
    const float* __restrict__ x, const float* __restrict__ w,
    const float* __restrict__ b, float* __restrict__ out)
{
    int row = blockIdx.x;
    int tid = threadIdx.x;
    const float* xr = x + (size_t)row * Dd;
    float4 v = *(const float4*)(xr + tid * 4);
    float s  = v.x + v.y + v.z + v.w;
    float sq = v.x*v.x + v.y*v.y + v.z*v.z + v.w*v.w;
    #pragma unroll
    for (int o = 16; o > 0; o >>= 1) {
        s  += __shfl_xor_sync(0xffffffffu, s,  o);
        sq += __shfl_xor_sync(0xffffffffu, sq, o);
    }
    __shared__ float ss[8], ssq[8];
    int wid = tid >> 5, lid = tid & 31;
    if (lid == 0) { ss[wid] = s; ssq[wid] = sq; }
    __syncthreads();
    s = 0.f; sq = 0.f;
    #pragma unroll
    for (int i = 0; i < 8; i++) { s += ss[i]; sq += ssq[i]; }
    float mu  = s * (1.f / Dd);
    float var = sq * (1.f / Dd) - mu * mu;
    float rs  = rsqrtf(var + 1e-5f);
    float4 wv = *(const float4*)(w + tid * 4);
    float4 bv = *(const float4*)(b + tid * 4);
    float4 o;
    o.x = (v.x - mu) * rs * wv.x + bv.x;
    o.y = (v.y - mu) * rs * wv.y + bv.y;
    o.z = (v.z - mu) * rs * wv.z + bv.z;
    o.w = (v.w - mu) * rs * wv.w + bv.w;
    *(float4*)(out + (size_t)row * Dd + tid * 4) = o;
}

// ---------------------------------------------------------------------------
// TF32 tensor-core GEMM with cp.async 3-stage pipeline.
// C = A[M,K] @ W[K,N] + bias; modes: 0 bias, 1 +res, 2 SiLU, 3 sigmoid.
// 128x128x16 tile, 256 threads. fp32 fed to HMMA.TF32 (HW truncates mantissa).
// ---------------------------------------------------------------------------
#define AST 20
#define BST 136
#define NSTG 3

__global__ __launch_bounds__(256) void tgemm_kernel(
    const float* __restrict__ A, const float* __restrict__ W,
    const float* __restrict__ bias, const float* __restrict__ res,
    float* __restrict__ C, int M, int N, int K, int mode)
{
    __shared__ float As[NSTG][128][AST];
    __shared__ float Bs[NSTG][16][BST];

    int t = threadIdx.x;
    int bm = blockIdx.y * 128;
    int bn = blockIdx.x * 128;
    int lane = t & 31, wid = t >> 5;
    int r = lane >> 2, q = lane & 3;
    int m_base = (wid & 3) * 32;
    int n_base = (wid >> 2) * 64;

    int a_row0 = t >> 2;           // 0..63 (+64 for second chunk)
    int a_kc   = (t & 3) * 4;
    int b_row0 = t >> 5;           // 0..7 (+8 for second chunk)
    int b_col  = (t & 31) * 4;

    const int nk = K / 16;

    const float* Abase = A + (size_t)(bm + a_row0) * K + a_kc;
    const float* Abase2 = Abase + (size_t)64 * K;
    const float* Wbase = W + (size_t)b_row0 * N + bn + b_col;
    const float* Wbase2 = Wbase + (size_t)8 * N;

    float acc[2][8][4];
    #pragma unroll
    for (int i = 0; i < 2; i++)
        #pragma unroll
        for (int j = 0; j < 8; j++)
            #pragma unroll
            for (int c = 0; c < 4; c++) acc[i][j][c] = 0.f;

    // prologue: issue stages 0,1
    #pragma unroll
    for (int s = 0; s < 2; s++) {
        int k0 = s * 16;
        cp_async16(&As[s][a_row0     ][a_kc], Abase  + k0);
        cp_async16(&As[s][a_row0 + 64][a_kc], Abase2 + k0);
        cp_async16(&Bs[s][b_row0     ][b_col], Wbase  + (size_t)k0 * N);
        cp_async16(&Bs[s][b_row0 + 8 ][b_col], Wbase2 + (size_t)k0 * N);
        cp_commit();
    }
    cp_wait<1>();
    __syncthreads();

    for (int kt = 0; kt < nk; kt++) {
        int buf = kt % NSTG;

        #pragma unroll
        for (int k8 = 0; k8 < 16; k8 += 8) {
            uint32_t a[2][4], b[8][2];
            #pragma unroll
            for (int mt = 0; mt < 2; mt++) {
                int m0 = m_base + mt * 16;
                a[mt][0] = __float_as_uint(As[buf][m0 + r    ][k8 + q]);
                a[mt][1] = __float_as_uint(As[buf][m0 + r + 8][k8 + q]);
                a[mt][2] = __float_as_uint(As[buf][m0 + r    ][k8 + q + 4]);
                a[mt][3] = __float_as_uint(As[buf][m0 + r + 8][k8 + q + 4]);
            }
            #pragma unroll
            for (int nt = 0; nt < 8; nt++) {
                int n0 = n_base + nt * 8;
                b[nt][0] = __float_as_uint(Bs[buf][k8 + q    ][n0 + r]);
                b[nt][1] = __float_as_uint(Bs[buf][k8 + q + 4][n0 + r]);
            }
            #pragma unroll
            for (int mt = 0; mt < 2; mt++)
                #pragma unroll
                for (int nt = 0; nt < 8; nt++)
                    mma_tf32(acc[mt][nt], a[mt], b[nt]);
        }

        // issue stage kt+2
        if (kt + 2 < nk) {
            int s  = (kt + 2) % NSTG;
            int k0 = (kt + 2) * 16;
            cp_async16(&As[s][a_row0     ][a_kc], Abase  + k0);
            cp_async16(&As[s][a_row0 + 64][a_kc], Abase2 + k0);
            cp_async16(&Bs[s][b_row0     ][b_col], Wbase  + (size_t)k0 * N);
            cp_async16(&Bs[s][b_row0 + 8 ][b_col], Wbase2 + (size_t)k0 * N);
        }
        cp_commit();
        cp_wait<1>();
        __syncthreads();
    }

    // epilogue
    #pragma unroll
    for (int mt = 0; mt < 2; mt++) {
        int row0 = bm + m_base + mt * 16 + r;
        #pragma unroll
        for (int nt = 0; nt < 8; nt++) {
            int col = bn + n_base + nt * 8 + q * 2;
            float b0 = bias[col], b1 = bias[col + 1];
            float v0 = acc[mt][nt][0] + b0;
            float v1 = acc[mt][nt][1] + b1;
            float v2 = acc[mt][nt][2] + b0;
            float v3 = acc[mt][nt][3] + b1;
            if (mode == 1) {
                v0 += res[(size_t)row0 * N + col];
                v1 += res[(size_t)row0 * N + col + 1];
                v2 += res[(size_t)(row0 + 8) * N + col];
                v3 += res[(size_t)(row0 + 8) * N + col + 1];
            } else if (mode == 2) {
                v0 = v0 / (1.f + __expf(-v0));
                v1 = v1 / (1.f + __expf(-v1));
                v2 = v2 / (1.f + __expf(-v2));
                v3 = v3 / (1.f + __expf(-v3));
            } else if (mode == 3) {
                v0 = 1.f / (1.f + __expf(-v0));
                v1 = 1.f / (1.f + __expf(-v1));
                v2 = 1.f / (1.f + __expf(-v2));
                v3 = 1.f / (1.f + __expf(-v3));
            }
            *(float2*)(C + (size_t)row0 * N + col)       = make_float2(v0, v1);
            *(float2*)(C + (size_t)(row0 + 8) * N + col) = make_float2(v2, v3);
        }
    }
}

// ---------------------------------------------------------------------------
// TF32 MMA flash attention (unchanged from round 5)
// ---------------------------------------------------------------------------
#define AT_KST 36
#define AT_VST 68
#define AT_SST 68
#define ATTN_SMEM ((64*AT_KST + 96*AT_VST + 4*16*AT_SST) * 4)

__global__ __launch_bounds__(128) void attn_mma_kernel(
    const float* __restrict__ q, const float* __restrict__ k,
    const float* __restrict__ v, float* __restrict__ y)
{
    extern __shared__ float sm[];
    float* Ks = sm;
    float* Vs = Ks + 64 * AT_KST;
    float* Ss = Vs + 96 * AT_VST;

    int tid  = threadIdx.x;
    int wid  = tid >> 5, lane = tid & 31;
    int r    = lane >> 2, qd = lane & 3;
    int qt   = blockIdx.x;
    int bh   = blockIdx.y;
    int b    = bh >> 4, h = bh & 15;
    int q0   = qt * 64;
    int mrow = wid * 16;

    const float* qbase = q + (size_t)b * Tt * DCc + h * CHD;
    const float* kbase = k + (size_t)b * Tt * DCc + h * CHD;
    const float* vbase = v + (size_t)b * Tt * DMm + h * MHD;

    const float scale = 0.17677669529663687f;
    int grow0 = q0 + mrow + r;
    uint32_t qa[4][4];
    #pragma unroll
    for (int ks = 0; ks < 4; ks++) {
        qa[ks][0] = f2tf32(qbase[(size_t)grow0       * DCc + ks * 8 + qd    ] * scale);
        qa[ks][1] = f2tf32(qbase[(size_t)(grow0 + 8) * DCc + ks * 8 + qd    ] * scale);
        qa[ks][2] = f2tf32(qbase[(size_t)grow0       * DCc + ks * 8 + qd + 4] * scale);
        qa[ks][3] = f2tf32(qbase[(size_t)(grow0 + 8) * DCc + ks * 8 + qd + 4] * scale);
    }

    float m0 = -1e30f, m1 = -1e30f, l0 = 0.f, l1 = 0.f;
    float o[12][4];
    #pragma unroll
    for (int nt = 0; nt < 12; nt++)
        #pragma unroll
        for (int c = 0; c < 4; c++) o[nt][c] = 0.f;

    float* Sw = Ss + wid * 16 * AT_SST;

    for (int j = 0; j <= qt; j++) {
        int k0 = j * 64;
        __syncthreads();
        {
            int row = tid >> 1;
            int c0  = (tid & 1) * 16;
            const float* src = kbase + (size_t)(k0 + row) * DCc + c0;
            uint32_t* dst = (uint32_t*)&Ks[row * AT_KST + c0];
            #pragma unroll
            for (int jj = 0; jj < 4; jj++) {
                float4 f = *(const float4*)(src + jj * 4);
                uint4 u = make_uint4(f2tf32(f.x), f2tf32(f.y), f2tf32(f.z), f2tf32(f.w));
                *(uint4*)(dst + jj * 4) = u;
            }
        }
        {
            #pragma unroll
            for (int it = 0; it < 12; it++) {
                int idx  = it * 128 + tid;
                int trow = idx / 24, c4 = idx % 24;
                float4 f = *(const float4*)(vbase + (size_t)(k0 + trow) * DMm + c4 * 4);
                Vs[(c4 * 4 + 0) * AT_VST + trow] = __uint_as_float(f2tf32(f.x));
                Vs[(c4 * 4 + 1) * AT_VST + trow] = __uint_as_float(f2tf32(f.y));
                Vs[(c4 * 4 + 2) * AT_VST + trow] = __uint_as_float(f2tf32(f.z));
                Vs[(c4 * 4 + 3) * AT_VST + trow] = __uint_as_float(f2tf32(f.w));
            }
        }
        __syncthreads();

        float sc[8][4];
        #pragma unroll
        for (int nt = 0; nt < 8; nt++)
            #pragma unroll
            for (int c = 0; c < 4; c++) sc[nt][c] = 0.f;
        #pragma unroll
        for (int ks = 0; ks < 4; ks++) {
            #pragma unroll
            for (int nt = 0; nt < 8; nt++) {
                uint32_t bb[2];
                bb[0] = __float_as_uint(Ks[(nt * 8 + r) * AT_KST + ks * 8 + qd    ]);
                bb[1] = __float_as_uint(Ks[(nt * 8 + r) * AT_KST + ks * 8 + qd + 4]);
                mma_tf32(sc[nt], qa[ks], bb);
            }
        }

        float mx0 = -1e30f, mx1 = -1e30f;
        #pragma unroll
        for (int nt = 0; nt < 8; nt++) {
            int c = k0 + nt * 8 + 2 * qd;
            if (c     > grow0    ) sc[nt][0] = -1e30f;
            if (c + 1 > grow0    ) sc[nt][1] = -1e30f;
            if (c     > grow0 + 8) sc[nt][2] = -1e30f;
            if (c + 1 > grow0 + 8) sc[nt][3] = -1e30f;
            mx0 = fmaxf(mx0, fmaxf(sc[nt][0], sc[nt][1]));
            mx1 = fmaxf(mx1, fmaxf(sc[nt][2], sc[nt][3]));
        }
        mx0 = fmaxf(mx0, __shfl_xor_sync(0xffffffffu, mx0, 1));
        mx0 = fmaxf(mx0, __shfl_xor_sync(0xffffffffu, mx0, 2));
        mx1 = fmaxf(mx1, __shfl_xor_sync(0xffffffffu, mx1, 1));
        mx1 = fmaxf(mx1, __shfl_xor_sync(0xffffffffu, mx1, 2));

        float mn0 = fmaxf(m0, mx0), mn1 = fmaxf(m1, mx1);
        float corr0 = __expf(m0 - mn0), corr1 = __expf(m1 - mn1);
        float s0 = 0.f, s1 = 0.f;
        #pragma unroll
        for (int nt = 0; nt < 8; nt++) {
            float p00 = __expf(sc[nt][0] - mn0);
            float p01 = __expf(sc[nt][1] - mn0);
            float p10 = __expf(sc[nt][2] - mn1);
            float p11 = __expf(sc[nt][3] - mn1);
            s0 += p00 + p01;
            s1 += p10 + p11;
            int cb = nt * 8 + 2 * qd;
            Sw[r * AT_SST + cb]           = __uint_as_float(f2tf32(p00));
            Sw[r * AT_SST + cb + 1]       = __uint_as_float(f2tf32(p01));
            Sw[(r + 8) * AT_SST + cb]     = __uint_as_float(f2tf32(p10));
            Sw[(r + 8) * AT_SST + cb + 1] = __uint_as_float(f2tf32(p11));
        }
        s0 += __shfl_xor_sync(0xffffffffu, s0, 1);
        s0 += __shfl_xor_sync(0xffffffffu, s0, 2);
        s1 += __shfl_xor_sync(0xffffffffu, s1, 1);
        s1 += __shfl_xor_sync(0xffffffffu, s1, 2);
        l0 = l0 * corr0 + s0;
        l1 = l1 * corr1 + s1;
        m0 = mn0; m1 = mn1;
        #pragma unroll
        for (int nt = 0; nt < 12; nt++) {
            o[nt][0] *= corr0; o[nt][1] *= corr0;
            o[nt][2] *= corr1; o[nt][3] *= corr1;
        }
        __syncwarp();

        #pragma unroll
        for (int ks = 0; ks < 8; ks++) {
            uint32_t pa[4];
            pa[0] = __float_as_uint(Sw[r       * AT_SST + ks * 8 + qd    ]);
            pa[1] = __float_as_uint(Sw[(r + 8) * AT_SST + ks * 8 + qd    ]);
            pa[2] = __float_as_uint(Sw[r       * AT_SST + ks * 8 + qd + 4]);
            pa[3] = __float_as_uint(Sw[(r + 8) * AT_SST + ks * 8 + qd + 4]);
            #pragma unroll
            for (int nt = 0; nt < 12; nt++) {
                uint32_t bb[2];
                bb[0] = __float_as_uint(Vs[(nt * 8 + r) * AT_VST + ks * 8 + qd    ]);
                bb[1] = __float_as_uint(Vs[(nt * 8 + r) * AT_VST + ks * 8 + qd + 4]);
                mma_tf32(o[nt], pa, bb);
            }
        }
        __syncwarp();
    }

    float inv0 = 1.f / l0, inv1 = 1.f / l1;
    float* yb = y + (size_t)b * Tt * DMm + h * MHD;
    #pragma unroll
    for (int nt = 0; nt < 12; nt++) {
        int cb = nt * 8 + 2 * qd;
        *(float2*)(yb + (size_t)grow0 * DMm + cb) =
            make_float2(o[nt][0] * inv0, o[nt][1] * inv0);
        *(float2*)(yb + (size_t)(grow0 + 8) * DMm + cb) =
            make_float2(o[nt][2] * inv1, o[nt][3] * inv1);
    }
}

// ---------------------------------------------------------------------------
// elementwise: e = silu(e * g)
// ---------------------------------------------------------------------------
__global__ __launch_bounds__(256) void eg_kernel(
    float* __restrict__ e, const float* __restrict__ g, int n4)
{
    int i = blockIdx.x * blockDim.x + threadIdx.x;
    if (i >= n4) return;
    float4 a = ((float4*)e)[i];
    float4 bb = ((const float4*)g)[i];
    float t;
    t = a.x * bb.x; a.x = t / (1.f + __expf(-t));
    t = a.y * bb.y; a.y = t / (1.f + __expf(-t));
    t = a.z * bb.z; a.z = t / (1.f + __expf(-t));
    t = a.w * bb.w; a.w = t / (1.f + __expf(-t));
    ((float4*)e)[i] = a;
}

// ---------------------------------------------------------------------------
// Host launcher
// ---------------------------------------------------------------------------
extern "C" void kernel_launch(void* const* d_in, const int* in_sizes, int n_in,
                              void* d_out, int out_size)
{
    const float* x     = (const float*)d_in[0];
    const float* ln1_w = (const float*)d_in[2];
    const float* ln1_b = (const float*)d_in[3];
    const float* wq    = (const float*)d_in[4];
    const float* bq    = (const float*)d_in[5];
    const float* wk    = (const float*)d_in[6];
    const float* bk    = (const float*)d_in[7];
    const float* wv    = (const float*)d_in[8];
    const float* bv    = (const float*)d_in[9];
    const float* wo    = (const float*)d_in[10];
    const float* bo    = (const float*)d_in[11];
    const float* ln2_w = (const float*)d_in[12];
    const float* ln2_b = (const float*)d_in[13];
    const float* we    = (const float*)d_in[14];
    const float* be    = (const float*)d_in[15];
    const float* wg    = (const float*)d_in[16];
    const float* bg    = (const float*)d_in[17];
    const float* wu    = (const float*)d_in[18];
    const float* bu    = (const float*)d_in[19];
    const float* wc    = (const float*)d_in[20];
    const float* bc    = (const float*)d_in[21];
    float* out = (float*)d_out;

    float *x1, *qp, *kp, *vp, *yp, *xa, *x2, *ep, *sg, *gp;
    cudaGetSymbolAddress((void**)&x1, g_x1);
    cudaGetSymbolAddress((void**)&qp, g_q);
    cudaGetSymbolAddress((void**)&kp, g_k);
    cudaGetSymbolAddress((void**)&vp, g_v);
    cudaGetSymbolAddress((void**)&yp, g_y);
    cudaGetSymbolAddress((void**)&xa, g_xa);
    cudaGetSymbolAddress((void**)&x2, g_x2);
    cudaGetSymbolAddress((void**)&ep, g_e);
    cudaGetSymbolAddress((void**)&sg, g_sg);
    cudaGetSymbolAddress((void**)&gp, g_g);

    cudaFuncSetAttribute(attn_mma_kernel,
                         cudaFuncAttributeMaxDynamicSharedMemorySize, ATTN_SMEM);

    // 1) LN1
    ln_kernel<<<Mrows, 256>>>(x, ln1_w, ln1_b, x1);

    // 2) Q/K/V projections
    tgemm_kernel<<<dim3(DCc/128, Mrows/128), 256>>>(x1, wq, bq, nullptr, qp, Mrows, DCc, Dd, 0);
    tgemm_kernel<<<dim3(DCc/128, Mrows/128), 256>>>(x1, wk, bk, nullptr, kp, Mrows, DCc, Dd, 0);
    tgemm_kernel<<<dim3(DMm/128, Mrows/128), 256>>>(x1, wv, bv, nullptr, vp, Mrows, DMm, Dd, 0);

    // 3) causal attention (TF32 MMA)
    attn_mma_kernel<<<dim3(Tt/64, Bq*Hh), 128, ATTN_SMEM>>>(qp, kp, vp, yp);

    // 4) output projection + residual
    tgemm_kernel<<<dim3(Dd/128, Mrows/128), 256>>>(yp, wo, bo, x, xa, Mrows, Dd, DMm, 1);

    // 5) LN2
    ln_kernel<<<Mrows, 256>>>(xa, ln2_w, ln2_b, x2);

    // 6) e = x2@we + be
    tgemm_kernel<<<dim3(DEe/128, Mrows/128), 256>>>(x2, we, be, nullptr, ep, Mrows, DEe, Dd, 0);

    // 7) sg = silu(x2@wg + bg)
    tgemm_kernel<<<dim3(DGg/128, Mrows/128), 256>>>(x2, wg, bg, nullptr, sg, Mrows, DGg, Dd, 2);

    // 8) g = sigmoid(sg@wu + bu)
    tgemm_kernel<<<dim3(DEe/128, Mrows/128), 256>>>(sg, wu, bu, nullptr, gp, Mrows, DEe, DGg, 3);

    // 9) e = silu(e * g)
    {
        int n4 = Mrows * DEe / 4;
        eg_kernel<<<(n4 + 255) / 256, 256>>>(ep, gp, n4);
    }

    // 10) out = xa + e@wc + bc
    tgemm_kernel<<<dim3(Dd/128, Mrows/128), 256>>>(ep, wc, bc, xa, out, Mrows, Dd, DEe, 1);
}